// round 6
// baseline (speedup 1.0000x reference)
#include <cuda_runtime.h>
#include <cuda_bf16.h>

#define BB 4
#define MM 2048
#define HH 16
#define NJ 12
#define SCALE 0.3535533905932738f   // (128//16)^-0.5

__constant__ float c_F[NJ] = {
    1.0f, 1.0f, 5.0e-1f, 1.6666666666666666e-1f,
    4.1666666666666664e-2f, 8.3333333333333332e-3f,
    1.3888888888888889e-3f, 1.9841269841269841e-4f,
    2.4801587301587302e-5f, 2.7557319223985893e-6f,
    2.7557319223985894e-7f, 2.5052108385441720e-8f
};

// cross-block LN state (zero-init; self-resetting each run)
__device__ float g_part [BB * HH];
__device__ float g_part2[BB * HH];
__device__ int   g_cnt [BB];
__device__ int   g_done[BB];
__device__ int   g_flag[BB];
__device__ float g_mu[BB], g_rs[BB];

__global__ void __launch_bounds__(256, 1)
k_fused(const float* __restrict__ query, const float* __restrict__ key_,
        const float* __restrict__ value, const float* __restrict__ wq,
        const float* __restrict__ wk,    const float* __restrict__ wv,
        const float* __restrict__ wf,    const float* __restrict__ lnw,
        const float* __restrict__ lnb,   float* __restrict__ out) {
    const int b   = blockIdx.x >> 4;
    const int h   = blockIdx.x & 15;
    const int tid = threadIdx.x;

    __shared__ float buf[8448];         // phase1: qf(4096)+kv(4352); phase2: Kpow/Qpow/iv
    __shared__ float Ash[256];          // A(s,t) at [s*16+t]
    __shared__ float Gsh[256];          // G(t,s) at [t*16+s]
    __shared__ float SA[NJ * 16];       // [j*16+t]
    __shared__ float AG[NJ * 16];       // [j*16+t]
    __shared__ float cz[16 * 16];       // [t*16+j]  (j<12 used)
    __shared__ float U [NJ * 16];       // [j*16+t]
    __shared__ float Wf[NJ];
    __shared__ float red0[4], red1[4];
    __shared__ float mu_s, rs_s;

    float* qf = buf;            // [s*256 + 4*d2 + c] = {q_2d2, f_2d2, q_2d2+1, f_2d2+1}
    float* kv = buf + 4096;     // [d2*68 + 4*t + c] = {k_2d2, v_2d2, k_2d2+1, v_2d2+1}

    // ---- per-thread inputs (registers) ----
    float qv = 0.f, kval = 0.f, vval = 0.f, lwv = 0.f, lbv = 0.f;
    if (tid < 128) {
        int gi = b * MM + h * 128 + tid;
        qv   = query[gi];
        kval = key_ [gi];
        vval = value[gi];
        lwv  = lnw[h * 128 + tid];
        lbv  = lnb[h * 128 + tid];
    }

    // ---- stage weights: interleaved float4 layouts ----
    {
        const float4* wq4 = (const float4*)wq;
        const float4* wk4 = (const float4*)wk;
        const float4* wv4 = (const float4*)wv;
        const float4* wf4 = (const float4*)wf;
#pragma unroll
        for (int k = 0; k < 2; k++) {
            int i4 = tid + k * 256;
            float4 a  = wq4[i4];
            float4 f  = wf4[i4];
            float4 kk = wk4[i4];
            float4 vv = wv4[i4];
            int st  = i4 >> 5;       // s (for wq/wf) or t (for wk/wv)
            int off = i4 & 31;       // d = 4*off .. 4*off+3
            float* q0 = qf + st * 256 + 8 * off;
            ((float4*)q0)[0] = make_float4(a.x, f.x, a.y, f.y);
            ((float4*)q0)[1] = make_float4(a.z, f.z, a.w, f.w);
            float* k0 = kv + (off * 2) * 68 + 4 * st;
            ((float4*)k0)[0] = make_float4(kk.x, vv.x, kk.y, vv.y);
            float* k1 = kv + (off * 2 + 1) * 68 + 4 * st;
            ((float4*)k1)[0] = make_float4(kk.z, vv.z, kk.w, vv.w);
        }
    }
    __syncthreads();

    // ---- A(s,t) and G(t,s): 256 dual dots, fully vectorized ----
    {
        int s = tid >> 4, t = tid & 15;
        const float4* qp = (const float4*)(qf + s * 256);
        const float4* kp = (const float4*)(kv + 4 * t);
        float a = 0.f, g = 0.f;
#pragma unroll 16
        for (int d2 = 0; d2 < 64; d2++) {
            float4 q = qp[d2];
            float4 x = kp[d2 * 17];
            a = fmaf(q.x, x.x, a);
            g = fmaf(q.y, x.y, g);
            a = fmaf(q.z, x.z, a);
            g = fmaf(q.w, x.w, g);
        }
        Ash[s * 16 + t] = SCALE * a;
        Gsh[t * 16 + s] = g;
    }
    __syncthreads();    // staging region dead -> overlay

    float* Kpow = buf;           // [j*128 + p]   1536
    float* Qpow = buf + 1536;    // [j*132 + p]   1584
    float* iv   = buf + 3120;    // [t*132 + p]   2112

    // ---- parallel: K/Q powers (warps 0-3)  ||  SA/AG series (warps 4-5, 4 lanes/t) ----
    if (tid < 128) {
        float kp = 1.f, qp = 1.f;
#pragma unroll
        for (int j = 0; j < NJ; j++) {
            Kpow[j * 128 + tid] = kp;
            Qpow[j * 132 + tid] = qp;
            kp *= kval;
            qp *= qv;
        }
    } else if (tid < 192) {
        int idx = tid - 128;
        int tt = idx >> 2, qq = idx & 3;
        float4 g4 = *(const float4*)(Gsh + tt * 16 + qq * 4);
        float a0 = Ash[(qq * 4 + 0) * 16 + tt];
        float a1 = Ash[(qq * 4 + 1) * 16 + tt];
        float a2 = Ash[(qq * 4 + 2) * 16 + tt];
        float a3 = Ash[(qq * 4 + 3) * 16 + tt];
        float p0 = 1.f, p1 = 1.f, p2 = 1.f, p3 = 1.f;
#pragma unroll
        for (int j = 0; j < NJ; j++) {
            float sa = (p0 + p1) + (p2 + p3);
            float ag = fmaf(p0, g4.x, fmaf(p1, g4.y, fmaf(p2, g4.z, p3 * g4.w)));
            sa += __shfl_xor_sync(0xffffffffu, sa, 1);
            sa += __shfl_xor_sync(0xffffffffu, sa, 2);
            ag += __shfl_xor_sync(0xffffffffu, ag, 1);
            ag += __shfl_xor_sync(0xffffffffu, ag, 2);
            if (qq == 0) { SA[j * 16 + tt] = sa; AG[j * 16 + tt] = ag; }
            p0 *= a0; p1 *= a1; p2 *= a2; p3 *= a3;
        }
    }
    __syncthreads();

    // ---- cz[t][j] = F_j * QM_j * SA_j(t),  QM_j = sum_p Q_p^j (broadcast float4 scan) ----
    if (tid < NJ * 16) {
        int j = tid >> 4, t = tid & 15;
        const float4* qp4 = (const float4*)(Qpow + j * 132);
        float4 acc = make_float4(0.f, 0.f, 0.f, 0.f);
#pragma unroll
        for (int q = 0; q < 32; q++) {
            float4 x = qp4[q];
            acc.x += x.x; acc.y += x.y; acc.z += x.z; acc.w += x.w;
        }
        float qm = (acc.x + acc.y) + (acc.z + acc.w);
        cz[t * 16 + j] = c_F[j] * qm * SA[j * 16 + t];
    }
    __syncthreads();

    // ---- Z(p,t) by Horner in K_p (vector cz loads); iv = V_p / Z ----
    if (tid < 128) {
        const float4* c4 = (const float4*)cz;
#pragma unroll
        for (int t = 0; t < 16; t++) {
            float4 c0 = c4[t * 4 + 0];
            float4 c1 = c4[t * 4 + 1];
            float4 c2 = c4[t * 4 + 2];
            float z = c2.w;
            z = fmaf(z, kval, c2.z);
            z = fmaf(z, kval, c2.y);
            z = fmaf(z, kval, c2.x);
            z = fmaf(z, kval, c1.w);
            z = fmaf(z, kval, c1.z);
            z = fmaf(z, kval, c1.y);
            z = fmaf(z, kval, c1.x);
            z = fmaf(z, kval, c0.w);
            z = fmaf(z, kval, c0.z);
            z = fmaf(z, kval, c0.y);
            z = fmaf(z, kval, c0.x);
            iv[t * 132 + tid] = __fdividef(vval, z);
        }
    }
    __syncthreads();

    // ---- U[j][t] = sum_p Kpow[j][p] * iv[t][p]  (all float4) ----
    if (tid < NJ * 16) {
        int j = tid >> 4, t = tid & 15;
        const float4* kp4 = (const float4*)(Kpow + j * 128);
        const float4* iv4 = (const float4*)(iv + t * 132);
        float u = 0.f;
#pragma unroll
        for (int q = 0; q < 32; q++) {
            float4 a = kp4[q], x = iv4[q];
            u = fmaf(a.x, x.x, u);
            u = fmaf(a.y, x.y, u);
            u = fmaf(a.z, x.z, u);
            u = fmaf(a.w, x.w, u);
        }
        U[j * 16 + t] = u;
    }
    __syncthreads();

    // ---- Wf[j] = F_j * sum_t AG[j][t] * U[j][t] ----
    if (tid < NJ) {
        const float4* u4 = (const float4*)(U  + tid * 16);
        const float4* a4 = (const float4*)(AG + tid * 16);
        float s = 0.f;
#pragma unroll
        for (int q = 0; q < 4; q++) {
            float4 u = u4[q], a = a4[q];
            s = fmaf(u.x, a.x, s);
            s = fmaf(u.y, a.y, s);
            s = fmaf(u.z, a.z, s);
            s = fmaf(u.w, a.w, s);
        }
        Wf[tid] = c_F[tid] * s;
    }
    __syncthreads();

    // ---- y = q + sum_j Wf[j] q^j ----
    float yv = 0.f;
    if (tid < 128) {
        float val = Wf[NJ - 1];
#pragma unroll
        for (int j = NJ - 2; j >= 0; j--) val = fmaf(val, qv, Wf[j]);
        yv = qv + val;
    }

    // ---- distributed LayerNorm: deterministic partials + flag broadcast ----
    float s1 = yv, s2v = yv * yv;
    if (tid < 128) {
#pragma unroll
        for (int o = 16; o; o >>= 1) {
            s1  += __shfl_down_sync(0xffffffffu, s1,  o);
            s2v += __shfl_down_sync(0xffffffffu, s2v, o);
        }
        if ((tid & 31) == 0) { red0[tid >> 5] = s1; red1[tid >> 5] = s2v; }
    }
    __syncthreads();
    if (tid == 0) {
        float ps  = (red0[0] + red0[1]) + (red0[2] + red0[3]);
        float ps2 = (red1[0] + red1[1]) + (red1[2] + red1[3]);
        g_part [b * HH + h] = ps;
        g_part2[b * HH + h] = ps2;
        __threadfence();
        int old = atomicAdd(&g_cnt[b], 1);
        if (old == HH - 1) {
            __threadfence();
            float S = 0.f, S2 = 0.f;
#pragma unroll
            for (int i = 0; i < HH; i++) {   // fixed order -> deterministic
                S  += ((volatile float*)g_part )[b * HH + i];
                S2 += ((volatile float*)g_part2)[b * HH + i];
            }
            float mu  = S * (1.0f / MM);
            float var = S2 * (1.0f / MM) - mu * mu;
            g_mu[b] = mu;
            g_rs[b] = rsqrtf(var + 1e-5f);
            __threadfence();
            ((volatile int*)g_flag)[b] = 1;
        }
        while (((volatile int*)g_flag)[b] == 0) { }
        __threadfence();
        mu_s = ((volatile float*)g_mu)[b];
        rs_s = ((volatile float*)g_rs)[b];
    }
    __syncthreads();
    if (tid < 128) {
        out[b * MM + h * 128 + tid] = (yv - mu_s) * rs_s * lwv + lbv;
    }
    __syncthreads();
    if (tid == 0) {
        __threadfence();
        int old = atomicAdd(&g_done[b], 1);
        if (old == HH - 1) {            // last block resets state for next replay
            g_cnt[b]  = 0;
            g_done[b] = 0;
            g_flag[b] = 0;
        }
    }
}

extern "C" void kernel_launch(void* const* d_in, const int* in_sizes, int n_in,
                              void* d_out, int out_size) {
    const float* query = (const float*)d_in[0];
    const float* key_  = (const float*)d_in[1];
    const float* value = (const float*)d_in[2];
    const float* wq    = (const float*)d_in[3];
    const float* wk    = (const float*)d_in[4];
    const float* wv    = (const float*)d_in[5];
    const float* wf    = (const float*)d_in[6];
    const float* lw    = (const float*)d_in[7];
    const float* lb    = (const float*)d_in[8];
    float* out = (float*)d_out;

    k_fused<<<BB * HH, 256>>>(query, key_, value, wq, wk, wv, wf, lw, lb, out);
}